// round 1
// baseline (speedup 1.0000x reference)
#include <cuda_runtime.h>
#include <cuda_bf16.h>
#include <math.h>

#define NN   100000
#define EE   1600000
#define HIDD 128
#define BB   512
#define LLAY 3
#define EPSV 1e-5f

// ---------------- scratch (device globals; allocation-free) ----------------
__device__ __align__(16) float g_x  [NN * HIDD];   // current activations
__device__ __align__(16) float g_xw [NN * HIDD];   // x @ W for current layer
__device__ __align__(16) float g_agg[NN * HIDD];   // aggregation buffer
__device__ __align__(16) float g_deg  [NN];
__device__ __align__(16) float g_dinv [NN];
__device__ __align__(16) float g_dinvs[NN];
__device__ __align__(16) float g_pool[BB * HIDD];
__device__ __align__(16) float g_cnt [BB];

// ---------------- helpers ----------------
__device__ __forceinline__ void red_add_v4(float* p, float4 v) {
    asm volatile("red.global.add.v4.f32 [%0], {%1, %2, %3, %4};"
                 :: "l"(p), "f"(v.x), "f"(v.y), "f"(v.z), "f"(v.w)
                 : "memory");
}

// ---------------- init (re-run every graph replay: deterministic) ----------
__global__ void k_init() {
    int i = blockIdx.x * blockDim.x + threadIdx.x;
    if (i < NN)        g_deg[i]  = 1.0f;      // self-loop
    if (i < BB * HIDD) g_pool[i] = 0.0f;
    if (i < BB)        g_cnt[i]  = 0.0f;
}

__global__ void k_deg(const int* __restrict__ dst) {
    int e = blockIdx.x * blockDim.x + threadIdx.x;
    if (e < EE) atomicAdd(&g_deg[dst[e]], 1.0f);
}

__global__ void k_norm() {
    int i = blockIdx.x * blockDim.x + threadIdx.x;
    if (i < NN) {
        float d = g_deg[i];
        g_dinv[i]  = 1.0f / d;
        g_dinvs[i] = 1.0f / sqrtf(d);
    }
}

// ---------------- GEMM: [M,128] @ [128,128] -------------------------------
// mode 0: g_x   = Xext @ W + bias                     (input projection)
// mode 1: g_xw  = g_x  @ W ;  g_agg = g_xw*dinv + bias (layer GEMM + agg init)
// Block tile 64x128, K=128 fully resident in smem. 256 thr, 8x4 microtile.
__global__ void k_gemm(const float* __restrict__ Xext,
                       const float* __restrict__ W,
                       const float* __restrict__ bias,
                       int M, int mode)
{
    extern __shared__ float sm[];
    float* Xs = sm;                 // [64][128]   32 KB
    float* Ws = sm + 64 * HIDD;     // [128][128]  64 KB

    const float* X = (mode == 0) ? Xext : g_x;
    const int row0 = blockIdx.x * 64;

    // load W tile (entire 128x128), coalesced float4
    {
        float4*       Ws4 = reinterpret_cast<float4*>(Ws);
        const float4* W4  = reinterpret_cast<const float4*>(W);
        #pragma unroll
        for (int i = 0; i < 16; i++)
            Ws4[threadIdx.x + 256 * i] = W4[threadIdx.x + 256 * i];
    }
    // load X tile (64 rows x 128), coalesced float4, zero-pad OOB rows
    {
        float4*       Xs4 = reinterpret_cast<float4*>(Xs);
        const float4* X4  = reinterpret_cast<const float4*>(X);
        #pragma unroll
        for (int i = 0; i < 8; i++) {
            int idx = threadIdx.x + 256 * i;    // 0..2047
            int r   = idx >> 5;                 // row in tile
            int kq  = idx & 31;                 // float4 index in k
            int gr  = row0 + r;
            Xs4[idx] = (gr < M) ? X4[gr * 32 + kq]
                                : make_float4(0.f, 0.f, 0.f, 0.f);
        }
    }
    __syncthreads();

    const int tn = threadIdx.x & 31;   // 32 column groups x 4
    const int tm = threadIdx.x >> 5;   // 8 row groups x 8
    float acc[8][4];
    #pragma unroll
    for (int r = 0; r < 8; r++)
        #pragma unroll
        for (int c = 0; c < 4; c++) acc[r][c] = 0.f;

    #pragma unroll 4
    for (int k = 0; k < 128; k++) {
        float4 w = *reinterpret_cast<const float4*>(&Ws[k * 128 + tn * 4]);
        #pragma unroll
        for (int r = 0; r < 8; r++) {
            float xv = Xs[(tm * 8 + r) * 128 + k];   // warp broadcast
            acc[r][0] = fmaf(xv, w.x, acc[r][0]);
            acc[r][1] = fmaf(xv, w.y, acc[r][1]);
            acc[r][2] = fmaf(xv, w.z, acc[r][2]);
            acc[r][3] = fmaf(xv, w.w, acc[r][3]);
        }
    }

    float4 bb = reinterpret_cast<const float4*>(bias)[tn];
    #pragma unroll
    for (int r = 0; r < 8; r++) {
        int gr = row0 + tm * 8 + r;
        if (gr >= M) continue;
        float4 v = make_float4(acc[r][0], acc[r][1], acc[r][2], acc[r][3]);
        if (mode == 0) {
            v.x += bb.x; v.y += bb.y; v.z += bb.z; v.w += bb.w;
            reinterpret_cast<float4*>(g_x)[gr * 32 + tn] = v;
        } else {
            reinterpret_cast<float4*>(g_xw)[gr * 32 + tn] = v;
            float di = g_dinv[gr];
            float4 a = make_float4(fmaf(v.x, di, bb.x), fmaf(v.y, di, bb.y),
                                   fmaf(v.z, di, bb.z), fmaf(v.w, di, bb.w));
            reinterpret_cast<float4*>(g_agg)[gr * 32 + tn] = a;
        }
    }
}

// ---------------- edge scatter: agg[dst] += xw[src] * enorm ----------------
// one warp per edge, one float4 per lane, vectorized L2 reduction
__global__ void k_scatter(const int* __restrict__ src, const int* __restrict__ dst) {
    int gid = blockIdx.x * blockDim.x + threadIdx.x;
    int e = gid >> 5;
    int j = gid & 31;
    if (e >= EE) return;
    int s = src[e];
    int d = dst[e];
    float en = g_dinvs[s] * g_dinvs[d];
    float4 v = reinterpret_cast<const float4*>(g_xw)[s * 32 + j];
    v.x *= en; v.y *= en; v.z *= en; v.w *= en;
    red_add_v4(&g_agg[d * 128 + j * 4], v);
}

// ---------------- LayerNorm + ReLU (+ residual), warp per row --------------
__global__ void k_ln(const float* __restrict__ gamma,
                     const float* __restrict__ beta,
                     float* __restrict__ dout, int add_res, int write_out)
{
    int t = blockIdx.x * blockDim.x + threadIdx.x;
    int n    = t >> 5;
    int lane = t & 31;
    if (n >= NN) return;

    float4 v = reinterpret_cast<const float4*>(g_agg)[n * 32 + lane];
    float s = v.x + v.y + v.z + v.w;
    float q = v.x * v.x + v.y * v.y + v.z * v.z + v.w * v.w;
    #pragma unroll
    for (int o = 16; o; o >>= 1) {
        s += __shfl_xor_sync(0xffffffffu, s, o);
        q += __shfl_xor_sync(0xffffffffu, q, o);
    }
    float mu  = s * (1.0f / 128.0f);
    float var = q * (1.0f / 128.0f) - mu * mu;
    float rs  = rsqrtf(var + EPSV);

    float4 gg = reinterpret_cast<const float4*>(gamma)[lane];
    float4 bt = reinterpret_cast<const float4*>(beta)[lane];
    float4 y;
    y.x = fmaxf(fmaf((v.x - mu) * rs, gg.x, bt.x), 0.f);
    y.y = fmaxf(fmaf((v.y - mu) * rs, gg.y, bt.y), 0.f);
    y.z = fmaxf(fmaf((v.z - mu) * rs, gg.z, bt.z), 0.f);
    y.w = fmaxf(fmaf((v.w - mu) * rs, gg.w, bt.w), 0.f);

    if (add_res) {
        float4 r = reinterpret_cast<const float4*>(g_x)[n * 32 + lane];
        y.x += r.x; y.y += r.y; y.z += r.z; y.w += r.w;
    }
    reinterpret_cast<float4*>(g_x)[n * 32 + lane] = y;
    if (write_out)
        reinterpret_cast<float4*>(dout)[n * 32 + lane] = y;
}

// ---------------- global mean pool ------------------------------------------
__global__ void k_pool(const int* __restrict__ batch_idx) {
    int t = blockIdx.x * blockDim.x + threadIdx.x;
    int n = t >> 5;
    int j = t & 31;
    if (n >= NN) return;
    int b = batch_idx[n];
    float4 v = reinterpret_cast<const float4*>(g_x)[n * 32 + j];
    red_add_v4(&g_pool[b * 128 + j * 4], v);
    if (j == 0) atomicAdd(&g_cnt[b], 1.0f);
}

__global__ void k_poolfin(float* __restrict__ dout) {
    int i = blockIdx.x * blockDim.x + threadIdx.x;
    if (i >= BB * HIDD) return;
    int b = i >> 7;
    dout[NN * HIDD + i] = g_pool[i] / fmaxf(g_cnt[b], 1.0f);
}

// ---------------- launch ------------------------------------------------------
extern "C" void kernel_launch(void* const* d_in, const int* in_sizes, int n_in,
                              void* d_out, int out_size)
{
    const float* nodes     = (const float*)d_in[0];
    const int*   edges     = (const int*)  d_in[1];
    // d_in[2] = edge_types (unused by reference)
    const int*   batch_idx = (const int*)  d_in[3];
    const float* w_in      = (const float*)d_in[4];
    const float* b_in      = (const float*)d_in[5];
    const float* gcn_w     = (const float*)d_in[6];
    const float* gcn_b     = (const float*)d_in[7];
    const float* ln_g      = (const float*)d_in[8];
    const float* ln_b      = (const float*)d_in[9];
    float*       out       = (float*)d_out;

    const int* src = edges;        // edges[0, :]
    const int* dst = edges + EE;   // edges[1, :]

    const int SMEM = (64 * HIDD + HIDD * HIDD) * sizeof(float);   // 96 KB
    cudaFuncSetAttribute(k_gemm, cudaFuncAttributeMaxDynamicSharedMemorySize, SMEM);

    const int T = 256;
    k_init<<<(NN + T - 1) / T, T>>>();
    k_deg <<<(EE + T - 1) / T, T>>>(dst);
    k_norm<<<(NN + T - 1) / T, T>>>();

    const int GEMM_GRID = (NN + 63) / 64;
    k_gemm<<<GEMM_GRID, T, SMEM>>>(nodes, w_in, b_in, NN, 0);

    for (int i = 0; i < LLAY; i++) {
        k_gemm   <<<GEMM_GRID, T, SMEM>>>(nullptr, gcn_w + i * HIDD * HIDD,
                                          gcn_b + i * HIDD, NN, 1);
        k_scatter<<<(EE * 32 + T - 1) / T, T>>>(src, dst);
        k_ln     <<<(NN * 32 + T - 1) / T, T>>>(ln_g + i * HIDD, ln_b + i * HIDD,
                                                out, (i > 0) ? 1 : 0,
                                                (i == LLAY - 1) ? 1 : 0);
    }

    k_pool   <<<(NN * 32 + T - 1) / T, T>>>(batch_idx);
    k_poolfin<<<(BB * HIDD + T - 1) / T, T>>>(out);
}

// round 3
// speedup vs baseline: 1.9186x; 1.9186x over previous
#include <cuda_runtime.h>
#include <cuda_bf16.h>
#include <math.h>
#include <stdint.h>

#define NN    100000
#define EE    1600000
#define HIDD  128
#define BB    512
#define LLAY  3
#define EPSV  1e-5f
#define NPART ((NN + 1023) / 1024)

// ---------------- scratch (device globals; allocation-free) ----------------
__device__ __align__(16) float g_x  [NN * HIDD];
__device__ __align__(16) float g_xw [NN * HIDD];
__device__ __align__(16) float g_dinv [NN];
__device__ __align__(16) float g_dinvs[NN];
__device__ __align__(16) float g_pool[BB * HIDD];
__device__ __align__(16) float g_cnt [BB];
// CSR
__device__ int   g_ecnt[NN];
__device__ int   g_cur [NN];
__device__ int   g_scan[NN];
__device__ int   g_rows[NN];
__device__ int   g_part [NPART];
__device__ int   g_partS[NPART];
__device__ int   g_csr_src[EE];
__device__ float g_csr_w  [EE];

// ---------------- helpers ----------------
__device__ __forceinline__ void red_add_v4(float* p, float4 v) {
    asm volatile("red.global.add.v4.f32 [%0], {%1, %2, %3, %4};"
                 :: "l"(p), "f"(v.x), "f"(v.y), "f"(v.z), "f"(v.w)
                 : "memory");
}
__device__ __forceinline__ uint64_t pack_dup(float v) {
    uint32_t u = __float_as_uint(v);
    uint64_t r;
    asm("mov.b64 %0, {%1, %1};" : "=l"(r) : "r"(u));
    return r;
}
__device__ __forceinline__ void ffma2(uint64_t& d, uint64_t a, uint64_t b) {
    asm("fma.rn.f32x2 %0, %1, %2, %0;" : "+l"(d) : "l"(a), "l"(b));
}

// ---------------- init (must cover ALL of NN for graph-replay determinism) --
__global__ void k_init() {
    int i = blockIdx.x * blockDim.x + threadIdx.x;
    if (i < NN)        { g_ecnt[i] = 0; g_cur[i] = 0; }
    if (i < BB * HIDD) g_pool[i] = 0.0f;
    if (i < BB)        g_cnt[i]  = 0.0f;
}

__global__ void k_deg(const int* __restrict__ dst) {
    int e = blockIdx.x * blockDim.x + threadIdx.x;
    if (e < EE) atomicAdd(&g_ecnt[dst[e]], 1);
}

__global__ void k_norm() {
    int i = blockIdx.x * blockDim.x + threadIdx.x;
    if (i < NN) {
        float d = (float)g_ecnt[i] + 1.0f;   // + self-loop
        g_dinv[i]  = 1.0f / d;
        g_dinvs[i] = rsqrtf(d);
    }
}

// ---------------- 3-pass exclusive scan of g_ecnt -> g_rows ----------------
__global__ void k_scan_blk() {
    __shared__ int sm[1024];
    int i = blockIdx.x * 1024 + threadIdx.x;
    int v = (i < NN) ? g_ecnt[i] : 0;
    sm[threadIdx.x] = v;
    __syncthreads();
    #pragma unroll
    for (int off = 1; off < 1024; off <<= 1) {
        int t = (threadIdx.x >= off) ? sm[threadIdx.x - off] : 0;
        __syncthreads();
        sm[threadIdx.x] += t;
        __syncthreads();
    }
    if (i < NN) g_scan[i] = sm[threadIdx.x];
    if (threadIdx.x == 1023) g_part[blockIdx.x] = sm[1023];
}

__global__ void k_scan_top() {
    if (threadIdx.x == 0) {
        int s = 0;
        for (int b = 0; b < NPART; b++) { s += g_part[b]; g_partS[b] = s; }
    }
}

__global__ void k_scan_fin() {
    int i = blockIdx.x * blockDim.x + threadIdx.x;
    if (i >= NN) return;
    int b = i >> 10;
    g_rows[i] = g_scan[i] - g_ecnt[i] + (b ? g_partS[b - 1] : 0);
}

// ---------------- CSR fill (order within row is nondeterministic; OK) ------
__global__ void k_fill(const int* __restrict__ src, const int* __restrict__ dst) {
    int e = blockIdx.x * blockDim.x + threadIdx.x;
    if (e >= EE) return;
    int s = src[e], d = dst[e];
    int slot = g_rows[d] + atomicAdd(&g_cur[d], 1);
    g_csr_src[slot] = s;
    g_csr_w[slot]   = g_dinvs[s] * g_dinvs[d];
}

// ---------------- GEMM: [M,128] @ [128,128], packed f32x2 FFMA -------------
// mode 0: g_x  = Xext @ W + bias   (input projection)
// mode 1: g_xw = g_x  @ W          (layer GEMM; epilogue fused into k_aggln)
__global__ void k_gemm(const float* __restrict__ Xext,
                       const float* __restrict__ W,
                       const float* __restrict__ bias,
                       int M, int mode)
{
    extern __shared__ float sm[];
    float* Xs = sm;                 // [64][128]   32 KB
    float* Ws = sm + 64 * HIDD;     // [128][128]  64 KB

    const float* X = (mode == 0) ? Xext : g_x;
    const int row0 = blockIdx.x * 64;

    {   // W tile, coalesced float4
        float4*       Ws4 = reinterpret_cast<float4*>(Ws);
        const float4* W4  = reinterpret_cast<const float4*>(W);
        #pragma unroll
        for (int i = 0; i < 16; i++)
            Ws4[threadIdx.x + 256 * i] = W4[threadIdx.x + 256 * i];
    }
    {   // X tile, coalesced float4, zero-pad OOB rows
        float4*       Xs4 = reinterpret_cast<float4*>(Xs);
        const float4* X4  = reinterpret_cast<const float4*>(X);
        #pragma unroll
        for (int i = 0; i < 8; i++) {
            int idx = threadIdx.x + 256 * i;
            int r   = idx >> 5;
            int kq  = idx & 31;
            int gr  = row0 + r;
            Xs4[idx] = (gr < M) ? X4[gr * 32 + kq]
                                : make_float4(0.f, 0.f, 0.f, 0.f);
        }
    }
    __syncthreads();

    const int tn = threadIdx.x & 31;
    const int tm = threadIdx.x >> 5;

    uint64_t acc[8][2];
    const uint64_t z = pack_dup(0.0f);
    #pragma unroll
    for (int r = 0; r < 8; r++) { acc[r][0] = z; acc[r][1] = z; }

    const ulonglong2* Ws2 = reinterpret_cast<const ulonglong2*>(Ws);
    const float*      Xrow = &Xs[tm * 8 * 128];

    #pragma unroll 4
    for (int k = 0; k < 128; k++) {
        ulonglong2 wp = Ws2[k * 32 + tn];          // (w.x,w.y),(w.z,w.w)
        #pragma unroll
        for (int r = 0; r < 8; r++) {
            uint64_t xd = pack_dup(Xrow[r * 128 + k]);  // (xv,xv)
            ffma2(acc[r][0], xd, wp.x);
            ffma2(acc[r][1], xd, wp.y);
        }
    }

    float4 bb = make_float4(0.f, 0.f, 0.f, 0.f);
    if (mode == 0) bb = reinterpret_cast<const float4*>(bias)[tn];

    #pragma unroll
    for (int r = 0; r < 8; r++) {
        int gr = row0 + tm * 8 + r;
        if (gr >= M) continue;
        float2 lo = *reinterpret_cast<float2*>(&acc[r][0]);
        float2 hi = *reinterpret_cast<float2*>(&acc[r][1]);
        float4 v = make_float4(lo.x + bb.x, lo.y + bb.y, hi.x + bb.z, hi.y + bb.w);
        if (mode == 0)
            reinterpret_cast<float4*>(g_x)[gr * 32 + tn] = v;
        else
            reinterpret_cast<float4*>(g_xw)[gr * 32 + tn] = v;
    }
}

// ------- fused: CSR gather-aggregate + self-loop + bias + LN + ReLU + res ---
__global__ void k_aggln(const float* __restrict__ bias,
                        const float* __restrict__ gamma,
                        const float* __restrict__ beta,
                        float* __restrict__ dout,
                        int add_res, int write_out)
{
    int t = blockIdx.x * blockDim.x + threadIdx.x;
    int n    = t >> 5;
    int lane = t & 31;
    if (n >= NN) return;

    const float4* xw4 = reinterpret_cast<const float4*>(g_xw);

    // self-loop term
    float di  = g_dinv[n];
    float4 sv = xw4[n * 32 + lane];
    float4 acc = make_float4(sv.x * di, sv.y * di, sv.z * di, sv.w * di);

    int beg = g_rows[n];
    int end = beg + g_ecnt[n];
    int k = beg;
    for (; k + 4 <= end; k += 4) {
        int   s0 = g_csr_src[k],   s1 = g_csr_src[k+1];
        int   s2 = g_csr_src[k+2], s3 = g_csr_src[k+3];
        float w0 = g_csr_w[k],   w1 = g_csr_w[k+1];
        float w2 = g_csr_w[k+2], w3 = g_csr_w[k+3];
        float4 v0 = xw4[s0 * 32 + lane];
        float4 v1 = xw4[s1 * 32 + lane];
        float4 v2 = xw4[s2 * 32 + lane];
        float4 v3 = xw4[s3 * 32 + lane];
        acc.x = fmaf(v0.x, w0, fmaf(v1.x, w1, fmaf(v2.x, w2, fmaf(v3.x, w3, acc.x))));
        acc.y = fmaf(v0.y, w0, fmaf(v1.y, w1, fmaf(v2.y, w2, fmaf(v3.y, w3, acc.y))));
        acc.z = fmaf(v0.z, w0, fmaf(v1.z, w1, fmaf(v2.z, w2, fmaf(v3.z, w3, acc.z))));
        acc.w = fmaf(v0.w, w0, fmaf(v1.w, w1, fmaf(v2.w, w2, fmaf(v3.w, w3, acc.w))));
    }
    for (; k < end; k++) {
        int s = g_csr_src[k];
        float w = g_csr_w[k];
        float4 v = xw4[s * 32 + lane];
        acc.x = fmaf(v.x, w, acc.x);
        acc.y = fmaf(v.y, w, acc.y);
        acc.z = fmaf(v.z, w, acc.z);
        acc.w = fmaf(v.w, w, acc.w);
    }

    float4 bv = reinterpret_cast<const float4*>(bias)[lane];
    acc.x += bv.x; acc.y += bv.y; acc.z += bv.z; acc.w += bv.w;

    // LayerNorm over 128 (warp reduce)
    float s = acc.x + acc.y + acc.z + acc.w;
    float q = acc.x*acc.x + acc.y*acc.y + acc.z*acc.z + acc.w*acc.w;
    #pragma unroll
    for (int o = 16; o; o >>= 1) {
        s += __shfl_xor_sync(0xffffffffu, s, o);
        q += __shfl_xor_sync(0xffffffffu, q, o);
    }
    float mu  = s * (1.0f / 128.0f);
    float var = q * (1.0f / 128.0f) - mu * mu;
    float rs  = rsqrtf(var + EPSV);

    float4 gg = reinterpret_cast<const float4*>(gamma)[lane];
    float4 bt = reinterpret_cast<const float4*>(beta)[lane];
    float4 y;
    y.x = fmaxf(fmaf((acc.x - mu) * rs, gg.x, bt.x), 0.f);
    y.y = fmaxf(fmaf((acc.y - mu) * rs, gg.y, bt.y), 0.f);
    y.z = fmaxf(fmaf((acc.z - mu) * rs, gg.z, bt.z), 0.f);
    y.w = fmaxf(fmaf((acc.w - mu) * rs, gg.w, bt.w), 0.f);

    if (add_res) {
        float4 r = reinterpret_cast<const float4*>(g_x)[n * 32 + lane];
        y.x += r.x; y.y += r.y; y.z += r.z; y.w += r.w;
    }
    reinterpret_cast<float4*>(g_x)[n * 32 + lane] = y;
    if (write_out)
        reinterpret_cast<float4*>(dout)[n * 32 + lane] = y;
}

// ---------------- global mean pool ------------------------------------------
__global__ void k_pool(const int* __restrict__ batch_idx) {
    int t = blockIdx.x * blockDim.x + threadIdx.x;
    int n = t >> 5;
    int j = t & 31;
    if (n >= NN) return;
    int b = batch_idx[n];
    float4 v = reinterpret_cast<const float4*>(g_x)[n * 32 + j];
    red_add_v4(&g_pool[b * 128 + j * 4], v);
    if (j == 0) atomicAdd(&g_cnt[b], 1.0f);
}

__global__ void k_poolfin(float* __restrict__ dout) {
    int i = blockIdx.x * blockDim.x + threadIdx.x;
    if (i >= BB * HIDD) return;
    int b = i >> 7;
    dout[NN * HIDD + i] = g_pool[i] / fmaxf(g_cnt[b], 1.0f);
}

// ---------------- launch ------------------------------------------------------
extern "C" void kernel_launch(void* const* d_in, const int* in_sizes, int n_in,
                              void* d_out, int out_size)
{
    const float* nodes     = (const float*)d_in[0];
    const int*   edges     = (const int*)  d_in[1];
    const int*   batch_idx = (const int*)  d_in[3];
    const float* w_in      = (const float*)d_in[4];
    const float* b_in      = (const float*)d_in[5];
    const float* gcn_w     = (const float*)d_in[6];
    const float* gcn_b     = (const float*)d_in[7];
    const float* ln_g      = (const float*)d_in[8];
    const float* ln_b      = (const float*)d_in[9];
    float*       out       = (float*)d_out;

    const int* src = edges;
    const int* dst = edges + EE;

    const int SMEM = (64 * HIDD + HIDD * HIDD) * sizeof(float);   // 96 KB
    cudaFuncSetAttribute(k_gemm, cudaFuncAttributeMaxDynamicSharedMemorySize, SMEM);

    const int T = 256;
    const int INIT_N = (NN > BB * HIDD) ? NN : (BB * HIDD);      // FIX: cover all of NN
    k_init<<<(INIT_N + T - 1) / T, T>>>();
    k_deg <<<(EE + T - 1) / T, T>>>(dst);
    k_norm<<<(NN + T - 1) / T, T>>>();

    k_scan_blk<<<NPART, 1024>>>();
    k_scan_top<<<1, 32>>>();
    k_scan_fin<<<(NN + T - 1) / T, T>>>();
    k_fill<<<(EE + T - 1) / T, T>>>(src, dst);

    const int GEMM_GRID = (NN + 63) / 64;
    k_gemm<<<GEMM_GRID, T, SMEM>>>(nodes, w_in, b_in, NN, 0);

    for (int i = 0; i < LLAY; i++) {
        k_gemm <<<GEMM_GRID, T, SMEM>>>(nullptr, gcn_w + i * HIDD * HIDD,
                                        nullptr, NN, 1);
        k_aggln<<<(NN * 32 + T - 1) / T, T>>>(gcn_b + i * HIDD,
                                              ln_g + i * HIDD, ln_b + i * HIDD,
                                              out, (i > 0) ? 1 : 0,
                                              (i == LLAY - 1) ? 1 : 0);
    }

    k_pool   <<<(NN * 32 + T - 1) / T, T>>>(batch_idx);
    k_poolfin<<<(BB * HIDD + T - 1) / T, T>>>(out);
}

// round 5
// speedup vs baseline: 2.3015x; 1.1995x over previous
#include <cuda_runtime.h>
#include <cuda_bf16.h>
#include <math.h>
#include <stdint.h>

#define NN    100000
#define EE    1600000
#define HIDD  128
#define BB    512
#define LLAY  3
#define EPSV  1e-5f
#define NPART ((NN + 1023) / 1024)

// ---------------- scratch (device globals; allocation-free) ----------------
__device__ __align__(16) float g_x  [NN * HIDD];
__device__ __align__(16) float g_xw [NN * HIDD];
__device__ __align__(16) float g_dinv [NN];
__device__ __align__(16) float g_dinvs[NN];
__device__ __align__(16) float g_pool[BB * HIDD];
__device__ __align__(16) float g_cnt [BB];
// CSR
__device__ int   g_ecnt[NN];
__device__ int   g_cur [NN];
__device__ int   g_scan[NN];
__device__ int   g_rows[NN];
__device__ int   g_part [NPART];
__device__ int   g_partS[NPART];
__device__ int   g_csr_src[EE];
__device__ float g_csr_w  [EE];

// ---------------- helpers ----------------
__device__ __forceinline__ void red_add_v4(float* p, float4 v) {
    asm volatile("red.global.add.v4.f32 [%0], {%1, %2, %3, %4};"
                 :: "l"(p), "f"(v.x), "f"(v.y), "f"(v.z), "f"(v.w)
                 : "memory");
}
__device__ __forceinline__ uint32_t smem_u32(const void* p) {
    uint32_t a;
    asm("{ .reg .u64 t; cvta.to.shared.u64 t, %1; cvt.u32.u64 %0, t; }"
        : "=r"(a) : "l"(p));
    return a;
}
__device__ __forceinline__ void ldm_x4(uint32_t* r, uint32_t addr) {
    asm volatile("ldmatrix.sync.aligned.m8n8.x4.shared.b16 {%0,%1,%2,%3}, [%4];"
                 : "=r"(r[0]), "=r"(r[1]), "=r"(r[2]), "=r"(r[3]) : "r"(addr));
}
__device__ __forceinline__ void ldm_x4_t(uint32_t* r, uint32_t addr) {
    asm volatile("ldmatrix.sync.aligned.m8n8.x4.trans.shared.b16 {%0,%1,%2,%3}, [%4];"
                 : "=r"(r[0]), "=r"(r[1]), "=r"(r[2]), "=r"(r[3]) : "r"(addr));
}
__device__ __forceinline__ void mma_bf16(float* c, const uint32_t* a,
                                         uint32_t b0, uint32_t b1) {
    asm volatile(
        "mma.sync.aligned.m16n8k16.row.col.f32.bf16.bf16.f32 "
        "{%0,%1,%2,%3}, {%4,%5,%6,%7}, {%8,%9}, {%0,%1,%2,%3};"
        : "+f"(c[0]), "+f"(c[1]), "+f"(c[2]), "+f"(c[3])
        : "r"(a[0]), "r"(a[1]), "r"(a[2]), "r"(a[3]), "r"(b0), "r"(b1));
}

// ---------------- init (covers all of NN — graph-replay determinism) --------
__global__ void k_init() {
    int i = blockIdx.x * blockDim.x + threadIdx.x;
    if (i < NN)        { g_ecnt[i] = 0; g_cur[i] = 0; }
    if (i < BB * HIDD) g_pool[i] = 0.0f;
    if (i < BB)        g_cnt[i]  = 0.0f;
}

__global__ void k_deg(const int* __restrict__ dst) {
    int e = blockIdx.x * blockDim.x + threadIdx.x;
    if (e < EE) atomicAdd(&g_ecnt[dst[e]], 1);
}

__global__ void k_norm() {
    int i = blockIdx.x * blockDim.x + threadIdx.x;
    if (i < NN) {
        float d = (float)g_ecnt[i] + 1.0f;
        g_dinv[i]  = 1.0f / d;
        g_dinvs[i] = rsqrtf(d);
    }
}

// ---------------- scan / CSR build ----------------
__global__ void k_scan_blk() {
    __shared__ int sm[1024];
    int i = blockIdx.x * 1024 + threadIdx.x;
    int v = (i < NN) ? g_ecnt[i] : 0;
    sm[threadIdx.x] = v;
    __syncthreads();
    #pragma unroll
    for (int off = 1; off < 1024; off <<= 1) {
        int t = (threadIdx.x >= off) ? sm[threadIdx.x - off] : 0;
        __syncthreads();
        sm[threadIdx.x] += t;
        __syncthreads();
    }
    if (i < NN) g_scan[i] = sm[threadIdx.x];
    if (threadIdx.x == 1023) g_part[blockIdx.x] = sm[1023];
}

__global__ void k_scan_top() {
    if (threadIdx.x == 0) {
        int s = 0;
        for (int b = 0; b < NPART; b++) { s += g_part[b]; g_partS[b] = s; }
    }
}

__global__ void k_scan_fin() {
    int i = blockIdx.x * blockDim.x + threadIdx.x;
    if (i >= NN) return;
    int b = i >> 10;
    g_rows[i] = g_scan[i] - g_ecnt[i] + (b ? g_partS[b - 1] : 0);
}

__global__ void k_fill(const int* __restrict__ src, const int* __restrict__ dst) {
    int e = blockIdx.x * blockDim.x + threadIdx.x;
    if (e >= EE) return;
    int s = src[e], d = dst[e];
    int slot = g_rows[d] + atomicAdd(&g_cur[d], 1);
    g_csr_src[slot] = s;
    g_csr_w[slot]   = g_dinvs[s] * g_dinvs[d];
}

// ======== GEMM: [M,128] @ [128,128], 3-pass split-bf16 mma.sync =============
// mode 0: g_x  = Xext @ W + bias     mode 1: g_xw = g_x @ W
// SMEM tiles (bf16, 272B row stride for conflict-free ldmatrix):
//   A_hi | A_lo : [128 rows][128 k]      W_hi | W_lo : [128 k][128 n]
#define GSTRIDE 272
#define GTILE   (128 * GSTRIDE)          // 34816 B
#define OFF_AHI 0
#define OFF_ALO (GTILE)
#define OFF_WHI (2 * GTILE)
#define OFF_WLO (3 * GTILE)
#define GSMEM   (4 * GTILE)              // 139264 B

__global__ void __launch_bounds__(256, 1)
k_gemm_mma(const float* __restrict__ Xext,
           const float* __restrict__ W,
           const float* __restrict__ bias,
           int M, int mode)
{
    extern __shared__ char smem[];
    const uint32_t smb = smem_u32(smem);
    const int tid  = threadIdx.x;
    const int row0 = blockIdx.x * 128;
    const float* X = (mode == 0) ? Xext : g_x;

    // ---- convert A tile (fp32 -> bf16 hi/lo), zero-pad OOB rows ----
    {
        const float2* X2 = reinterpret_cast<const float2*>(X);
        #pragma unroll
        for (int i = 0; i < 32; i++) {
            int idx = tid + 256 * i;          // 0..8191 float2-pairs
            int row = idx >> 6;
            int kp  = idx & 63;
            int gr  = row0 + row;
            float2 v = (gr < M) ? X2[gr * 64 + kp] : make_float2(0.f, 0.f);
            __nv_bfloat162 h2 = __float22bfloat162_rn(v);
            float2 hf = __bfloat1622float2(h2);
            __nv_bfloat162 l2 = __float22bfloat162_rn(
                                   make_float2(v.x - hf.x, v.y - hf.y));
            int off = row * GSTRIDE + kp * 4;
            *reinterpret_cast<uint32_t*>(smem + OFF_AHI + off) =
                *reinterpret_cast<uint32_t*>(&h2);
            *reinterpret_cast<uint32_t*>(smem + OFF_ALO + off) =
                *reinterpret_cast<uint32_t*>(&l2);
        }
    }
    // ---- convert W tile (already [k][n] row-major) ----
    {
        const float2* W2 = reinterpret_cast<const float2*>(W);
        #pragma unroll
        for (int i = 0; i < 32; i++) {
            int idx = tid + 256 * i;
            int k   = idx >> 6;
            int np  = idx & 63;
            float2 v = W2[k * 64 + np];
            __nv_bfloat162 h2 = __float22bfloat162_rn(v);
            float2 hf = __bfloat1622float2(h2);
            __nv_bfloat162 l2 = __float22bfloat162_rn(
                                   make_float2(v.x - hf.x, v.y - hf.y));
            int off = k * GSTRIDE + np * 4;
            *reinterpret_cast<uint32_t*>(smem + OFF_WHI + off) =
                *reinterpret_cast<uint32_t*>(&h2);
            *reinterpret_cast<uint32_t*>(smem + OFF_WLO + off) =
                *reinterpret_cast<uint32_t*>(&l2);
        }
    }
    __syncthreads();

    const int wid  = tid >> 5;
    const int lane = tid & 31;
    const int wm   = wid >> 1;          // 0..3  -> 32-row strip
    const int wn   = wid & 1;           // 0..1  -> 64-col strip
    const int mb   = wm * 32;
    const int nb   = wn * 64;

    // ldmatrix lane addressing
    const int a_r  = lane & 15;                 // A: row within 16
    const int a_kb = (lane >> 4) << 4;          // A: 0 or 16 bytes (8 bf16)
    const int b_r  = lane & 7;                  // B: k-row within 8
    const int b_kh = ((lane >> 3) & 1) << 3;    // B: +8 k rows
    const int b_nh = ((lane >> 4) & 1) << 3;    // B: +8 n cols

    float acc[2][8][4];
    #pragma unroll
    for (int mt = 0; mt < 2; mt++)
        #pragma unroll
        for (int nt = 0; nt < 8; nt++)
            #pragma unroll
            for (int q = 0; q < 4; q++) acc[mt][nt][q] = 0.f;

    const uint32_t passA[3] = {OFF_AHI, OFF_AHI, OFF_ALO};
    const uint32_t passB[3] = {OFF_WHI, OFF_WLO, OFF_WHI};

    #pragma unroll
    for (int p = 0; p < 3; p++) {
        uint32_t Ab = smb + passA[p];
        uint32_t Bb = smb + passB[p];
        #pragma unroll
        for (int ks = 0; ks < 8; ks++) {
            uint32_t a[2][4];
            ldm_x4(a[0], Ab + (mb + a_r) * GSTRIDE + ks * 32 + a_kb);
            ldm_x4(a[1], Ab + (mb + 16 + a_r) * GSTRIDE + ks * 32 + a_kb);
            #pragma unroll
            for (int np = 0; np < 4; np++) {
                uint32_t b[4];
                ldm_x4_t(b, Bb + (ks * 16 + b_kh + b_r) * GSTRIDE
                             + (nb + np * 16 + b_nh) * 2);
                mma_bf16(acc[0][np*2],   a[0], b[0], b[1]);
                mma_bf16(acc[0][np*2+1], a[0], b[2], b[3]);
                mma_bf16(acc[1][np*2],   a[1], b[0], b[1]);
                mma_bf16(acc[1][np*2+1], a[1], b[2], b[3]);
            }
        }
    }

    // ---- epilogue: direct stores (c frag: rows t/4 & t/4+8, cols (t%4)*2) ----
    float* dst = (mode == 0) ? g_x : g_xw;
    const int tq = lane >> 2;
    const int tr = (lane & 3) * 2;
    #pragma unroll
    for (int mt = 0; mt < 2; mt++) {
        int rbase = row0 + mb + mt * 16 + tq;
        #pragma unroll
        for (int nt = 0; nt < 8; nt++) {
            int col = nb + nt * 8 + tr;
            float2 v0 = make_float2(acc[mt][nt][0], acc[mt][nt][1]);
            float2 v1 = make_float2(acc[mt][nt][2], acc[mt][nt][3]);
            if (mode == 0) {
                float2 bv = *reinterpret_cast<const float2*>(&bias[col]);
                v0.x += bv.x; v0.y += bv.y;
                v1.x += bv.x; v1.y += bv.y;
            }
            if (rbase < M)
                *reinterpret_cast<float2*>(&dst[rbase * 128 + col]) = v0;
            if (rbase + 8 < M)
                *reinterpret_cast<float2*>(&dst[(rbase + 8) * 128 + col]) = v1;
        }
    }
}

// ------- fused: CSR gather-aggregate + self-loop + bias + LN + ReLU + res ---
__global__ void k_aggln(const float* __restrict__ bias,
                        const float* __restrict__ gamma,
                        const float* __restrict__ beta,
                        float* __restrict__ dout,
                        int add_res, int write_out)
{
    int t = blockIdx.x * blockDim.x + threadIdx.x;
    int n    = t >> 5;
    int lane = t & 31;
    if (n >= NN) return;

    const float4* xw4 = reinterpret_cast<const float4*>(g_xw);

    float di  = g_dinv[n];
    float4 sv = xw4[n * 32 + lane];
    float4 acc = make_float4(sv.x * di, sv.y * di, sv.z * di, sv.w * di);

    int beg = g_rows[n];
    int end = beg + g_ecnt[n];
    int k = beg;
    for (; k + 4 <= end; k += 4) {
        int   s0 = g_csr_src[k],   s1 = g_csr_src[k+1];
        int   s2 = g_csr_src[k+2], s3 = g_csr_src[k+3];
        float w0 = g_csr_w[k],   w1 = g_csr_w[k+1];
        float w2 = g_csr_w[k+2], w3 = g_csr_w[k+3];
        float4 v0 = xw4[s0 * 32 + lane];
        float4 v1 = xw4[s1 * 32 + lane];
        float4 v2 = xw4[s2 * 32 + lane];
        float4 v3 = xw4[s3 * 32 + lane];
        acc.x = fmaf(v0.x, w0, fmaf(v1.x, w1, fmaf(v2.x, w2, fmaf(v3.x, w3, acc.x))));
        acc.y = fmaf(v0.y, w0, fmaf(v1.y, w1, fmaf(v2.y, w2, fmaf(v3.y, w3, acc.y))));
        acc.z = fmaf(v0.z, w0, fmaf(v1.z, w1, fmaf(v2.z, w2, fmaf(v3.z, w3, acc.z))));
        acc.w = fmaf(v0.w, w0, fmaf(v1.w, w1, fmaf(v2.w, w2, fmaf(v3.w, w3, acc.w))));
    }
    for (; k < end; k++) {
        int s = g_csr_src[k];
        float w = g_csr_w[k];
        float4 v = xw4[s * 32 + lane];
        acc.x = fmaf(v.x, w, acc.x);
        acc.y = fmaf(v.y, w, acc.y);
        acc.z = fmaf(v.z, w, acc.z);
        acc.w = fmaf(v.w, w, acc.w);
    }

    float4 bv = reinterpret_cast<const float4*>(bias)[lane];
    acc.x += bv.x; acc.y += bv.y; acc.z += bv.z; acc.w += bv.w;

    float s = acc.x + acc.y + acc.z + acc.w;
    float q = acc.x*acc.x + acc.y*acc.y + acc.z*acc.z + acc.w*acc.w;
    #pragma unroll
    for (int o = 16; o; o >>= 1) {
        s += __shfl_xor_sync(0xffffffffu, s, o);
        q += __shfl_xor_sync(0xffffffffu, q, o);
    }
    float mu  = s * (1.0f / 128.0f);
    float var = q * (1.0f / 128.0f) - mu * mu;
    float rs  = rsqrtf(var + EPSV);

    float4 gg = reinterpret_cast<const float4*>(gamma)[lane];
    float4 bt = reinterpret_cast<const float4*>(beta)[lane];
    float4 y;
    y.x = fmaxf(fmaf((acc.x - mu) * rs, gg.x, bt.x), 0.f);
    y.y = fmaxf(fmaf((acc.y - mu) * rs, gg.y, bt.y), 0.f);
    y.z = fmaxf(fmaf((acc.z - mu) * rs, gg.z, bt.z), 0.f);
    y.w = fmaxf(fmaf((acc.w - mu) * rs, gg.w, bt.w), 0.f);

    if (add_res) {
        float4 r = reinterpret_cast<const float4*>(g_x)[n * 32 + lane];
        y.x += r.x; y.y += r.y; y.z += r.z; y.w += r.w;
    }
    reinterpret_cast<float4*>(g_x)[n * 32 + lane] = y;
    if (write_out)
        reinterpret_cast<float4*>(dout)[n * 32 + lane] = y;
}

// ---------------- global mean pool ------------------------------------------
__global__ void k_pool(const int* __restrict__ batch_idx) {
    int t = blockIdx.x * blockDim.x + threadIdx.x;
    int n = t >> 5;
    int j = t & 31;
    if (n >= NN) return;
    int b = batch_idx[n];
    float4 v = reinterpret_cast<const float4*>(g_x)[n * 32 + j];
    red_add_v4(&g_pool[b * 128 + j * 4], v);
    if (j == 0) atomicAdd(&g_cnt[b], 1.0f);
}

__global__ void k_poolfin(float* __restrict__ dout) {
    int i = blockIdx.x * blockDim.x + threadIdx.x;
    if (i >= BB * HIDD) return;
    int b = i >> 7;
    dout[NN * HIDD + i] = g_pool[i] / fmaxf(g_cnt[b], 1.0f);
}

// ---------------- launch ------------------------------------------------------
extern "C" void kernel_launch(void* const* d_in, const int* in_sizes, int n_in,
                              void* d_out, int out_size)
{
    const float* nodes     = (const float*)d_in[0];
    const int*   edges     = (const int*)  d_in[1];
    const int*   batch_idx = (const int*)  d_in[3];
    const float* w_in      = (const float*)d_in[4];
    const float* b_in      = (const float*)d_in[5];
    const float* gcn_w     = (const float*)d_in[6];
    const float* gcn_b     = (const float*)d_in[7];
    const float* ln_g      = (const float*)d_in[8];
    const float* ln_b      = (const float*)d_in[9];
    float*       out       = (float*)d_out;

    const int* src = edges;
    const int* dst = edges + EE;

    cudaFuncSetAttribute(k_gemm_mma, cudaFuncAttributeMaxDynamicSharedMemorySize, GSMEM);

    const int T = 256;
    const int INIT_N = (NN > BB * HIDD) ? NN : (BB * HIDD);
    k_init<<<(INIT_N + T - 1) / T, T>>>();
    k_deg <<<(EE + T - 1) / T, T>>>(dst);
    k_norm<<<(NN + T - 1) / T, T>>>();

    k_scan_blk<<<NPART, 1024>>>();
    k_scan_top<<<1, 32>>>();
    k_scan_fin<<<(NN + T - 1) / T, T>>>();
    k_fill<<<(EE + T - 1) / T, T>>>(src, dst);

    const int GEMM_GRID = (NN + 127) / 128;
    k_gemm_mma<<<GEMM_GRID, T, GSMEM>>>(nodes, w_in, b_in, NN, 0);

    for (int i = 0; i < LLAY; i++) {
        k_gemm_mma<<<GEMM_GRID, T, GSMEM>>>(nullptr, gcn_w + i * HIDD * HIDD,
                                            nullptr, NN, 1);
        k_aggln<<<(NN * 32 + T - 1) / T, T>>>(gcn_b + i * HIDD,
                                              ln_g + i * HIDD, ln_b + i * HIDD,
                                              out, (i > 0) ? 1 : 0,
                                              (i == LLAY - 1) ? 1 : 0);
    }

    k_pool   <<<(NN * 32 + T - 1) / T, T>>>(batch_idx);
    k_poolfin<<<(BB * HIDD + T - 1) / T, T>>>(out);
}